// round 7
// baseline (speedup 1.0000x reference)
#include <cuda_runtime.h>
#include <cstdint>
#include <cstddef>

#define NEGV -1e30f

constexpr int Bb = 32, Tt = 256, S = 258, Q = 20;

// u vectors for the emission stage: u[x][b][20]
__device__ float g_uF[S * Bb * Q];
__device__ float g_uB[S * Bb * Q];

typedef unsigned long long ull;

// ---- helpers --------------------------------------------------------------
__device__ __forceinline__ ull pk2(float lo, float hi) {
    ull r;
    asm("mov.b64 %0, {%1, %2};" : "=l"(r) : "f"(lo), "f"(hi));
    return r;
}
__device__ __forceinline__ void upk2(float& lo, float& hi, ull v) {
    asm("mov.b64 {%0, %1}, %2;" : "=f"(lo), "=f"(hi) : "l"(v));
}
__device__ __forceinline__ void ffma2(ull& d, ull a, ull b) {
    asm("fma.rn.f32x2 %0, %1, %2, %0;" : "+l"(d) : "l"(a), "l"(b));
}
__device__ __forceinline__ void fadd2(ull& d, ull a) {
    asm("add.rn.f32x2 %0, %0, %1;" : "+l"(d) : "l"(a));
}
__device__ __forceinline__ float tanh_ap(float x) {
    float y;
    asm("tanh.approx.f32 %0, %1;" : "=f"(y) : "f"(x));
    return y;
}
__device__ __forceinline__ uint32_t s2u(const void* p) {
    uint32_t a;
    asm("{ .reg .u64 t; cvta.to.shared.u64 t, %1; cvt.u32.u64 %0, t; }"
        : "=r"(a) : "l"(p));
    return a;
}
__device__ __forceinline__ void cp_async16(uint32_t dst, const void* src) {
    asm volatile("cp.async.ca.shared.global [%0], [%1], 16;" :: "r"(dst), "l"(src));
}
__device__ __forceinline__ void cp_commit() {
    asm volatile("cp.async.commit_group;" ::: "memory");
}
template <int N> __device__ __forceinline__ void cp_wait() {
    asm volatile("cp.async.wait_group %0;" :: "n"(N) : "memory");
}
#define BAR_ARRIVE(id) asm volatile("bar.arrive %0, %1;" :: "r"(id), "r"(96) : "memory")
#define BAR_SYNC(id)   asm volatile("bar.sync %0, %1;"   :: "r"(id), "r"(96) : "memory")

// ---- fused kernel shared layout ------------------------------------------
struct __align__(16) SML {
    float pre[S][80];        // pre-gates [it][gt*20+q]              82560 B
    float W[128][80];        // W_ih                                 40960 B
    float A[2][32][128];     // embedding chunk ring                 32768 B
    float hist[S][20];       // h history (by position s)            20640 B
    float w1s[20][20];       // W1 rows for this dir                  1600 B
    float bias[80];
    float act[80];
    float hsh[32];
    int   tok[260];
};                           // ~180 KB

// ---------------------------------------------------------------------------
// Fused kernel: one block per (dir, batch), 352 threads.
//  warps 0..7: producers — chunked input-gate GEMM into sm.pre (cp.async ring)
//  warps 8..10: recurrence crew — lane = one gate; arrive/sync split barriers
//  epilogue: all threads compute u = hist @ W1dir -> g_uF/g_uB
// ---------------------------------------------------------------------------
__global__ __launch_bounds__(352, 1) void k12_fused(
    const int* __restrict__ x, const float* __restrict__ emb,
    const float* __restrict__ Wif, const float* __restrict__ bfv,
    const float* __restrict__ Wib, const float* __restrict__ bbv,
    const float* __restrict__ Whf, const float* __restrict__ Whb,
    const float* __restrict__ W1g)
{
    extern __shared__ char raw[];
    SML& sm = *(SML*)raw;
    const int tid = threadIdx.x;
    const int dir = blockIdx.x >> 5;
    const int b = blockIdx.x & 31;
    const float* Wih = dir ? Wib : Wif;
    const float* bia = dir ? bbv : bfv;
    const float* Whh = dir ? Whb : Whf;
    const bool isProd = (tid < 256);

    if (tid < 256) sm.tok[tid + 1] = x[b * Tt + tid];
    if (tid == 256) { sm.tok[0] = 2; sm.tok[S - 1] = 3; }
    if (tid < 80) sm.bias[tid] = bia[tid];

    // ---- crew setup ----
    const int ct = tid - 256;                 // 0..95 for crew
    const int lane = tid & 31;
    const bool gact = (ct >= 0) && (ct < 80);
    const int gcl = gact ? ct : 79;
    const int ggt = gcl / 20, gq = gcl % 20;
    const float szc = (ggt == 2) ? 1.f : 0.5f;
    const float aac = (ggt == 2) ? 1.f : 0.5f;
    const float bbc = (ggt == 2) ? 0.f : 0.5f;
    const bool isCrew = (tid >= 256);
    const bool isW10 = (tid >= 320);          // warp 10
    ull wk[10];
    float creg = 0.f;
    if (isCrew) {
#pragma unroll
        for (int j = 0; j < 10; j++)
            wk[j] = pk2(Whh[(2 * j) * 80 + gcl], Whh[(2 * j + 1) * 80 + gcl]);
        if (ct < 32) sm.hsh[ct] = 0.f;
    }
    __syncthreads();

    // ---- producer prologue: W_ih, A chunk 0 ----
    if (isProd) {
#pragma unroll
        for (int i = 0; i < 10; i++) {
            int f = tid + i * 256;
            cp_async16(s2u((char*)sm.W + f * 16), Wih + f * 4);
        }
        cp_commit();
#pragma unroll
        for (int i = 0; i < 4; i++) {
            int f = tid + i * 256;
            int rr = f >> 5, k4 = f & 31;
            int s = dir ? (S - 1 - rr) : rr;
            cp_async16(s2u(&sm.A[0][rr][k4 * 4]),
                       emb + (size_t)sm.tok[s] * 128 + k4 * 4);
        }
        cp_commit();
    }

    const int r = tid >> 3;
    const int c0 = (tid & 7) * 10;

    // one crew step; prez = this step's pre-gate (preloaded)
    auto crew_step = [&](int it, float& prez, int next_it) {
        const ulonglong2* hp = (const ulonglong2*)sm.hsh;
        ulonglong2 h0 = hp[0], h1 = hp[1], h2 = hp[2], h3 = hp[3], h4 = hp[4];
        ull acc0 = pk2(prez, 0.f), acc1 = 0ull;
        ffma2(acc0, h0.x, wk[0]); ffma2(acc1, h0.y, wk[1]);
        ffma2(acc0, h1.x, wk[2]); ffma2(acc1, h1.y, wk[3]);
        ffma2(acc0, h2.x, wk[4]); ffma2(acc1, h2.y, wk[5]);
        ffma2(acc0, h3.x, wk[6]); ffma2(acc1, h3.y, wk[7]);
        ffma2(acc0, h4.x, wk[8]); ffma2(acc1, h4.y, wk[9]);
        fadd2(acc0, acc1);
        float lo, hi;
        upk2(lo, hi, acc0);
        float z = lo + hi;
        float av = fmaf(tanh_ap(szc * z), aac, bbc);
        if (gact) sm.act[gq * 4 + ggt] = av;
        if (!isW10) {
            BAR_ARRIVE(1);
            if (next_it >= 0) prez = sm.pre[next_it][gcl];   // dead-window prefetch
            BAR_SYNC(2);
        } else {
            BAR_SYNC(1);
            if (lane < 20) {
                float4 ga = *(const float4*)&sm.act[lane * 4];   // i,f,g,o
                creg = fmaf(ga.y, creg, ga.x * ga.z);
                float h = ga.w * tanh_ap(creg);
                sm.hsh[lane] = h;
                int s = dir ? (S - 1 - it) : it;
                sm.hist[s][lane] = h;
            }
            __syncwarp();
            BAR_ARRIVE(2);
            if (next_it >= 0) prez = sm.pre[next_it][gcl];
        }
    };

    for (int ch = 0; ch < 9; ch++) {
        if (isProd) {
            if (ch < 8) {
#pragma unroll
                for (int i = 0; i < 4; i++) {
                    int f = tid + i * 256;
                    int rr = f >> 5, k4 = f & 31;
                    int itn = (ch + 1) * 32 + rr;
                    if (itn < S) {
                        int s = dir ? (S - 1 - itn) : itn;
                        cp_async16(s2u(&sm.A[(ch + 1) & 1][rr][k4 * 4]),
                                   emb + (size_t)sm.tok[s] * 128 + k4 * 4);
                    }
                }
            }
            cp_commit();
            cp_wait<1>();

            int it = ch * 32 + r;
            if (it < S) {
                const float* Arow = sm.A[ch & 1][r];
                ull acc[5] = {0ull, 0ull, 0ull, 0ull, 0ull};
#pragma unroll 4
                for (int k = 0; k < 128; k++) {
                    float a = Arow[k];
                    ull ap = pk2(a, a);
#pragma unroll
                    for (int j = 0; j < 5; j++)
                        ffma2(acc[j], ap, *(const ull*)&sm.W[k][c0 + 2 * j]);
                }
#pragma unroll
                for (int j = 0; j < 5; j++) {
                    float lo, hi;
                    upk2(lo, hi, acc[j]);
                    float2 v;
                    v.x = lo + sm.bias[c0 + 2 * j];
                    v.y = hi + sm.bias[c0 + 2 * j + 1];
                    *(float2*)&sm.pre[it][c0 + 2 * j] = v;
                }
            }
        } else if (ch > 0) {
            int base = (ch - 1) * 32;
            float prez = sm.pre[base][gcl];
            for (int i = 0; i < 31; i++) crew_step(base + i, prez, base + i + 1);
            crew_step(base + 31, prez, -1);
        }
        __syncthreads();
    }

    if (isCrew) {
        float prez = sm.pre[256][gcl];
        crew_step(256, prez, 257);
        crew_step(257, prez, -1);
    }
    __syncthreads();

    // ---- u-phase: u[x] = hist[x] @ W1dir  (W1F = rows 0..19, W1B = 20..39)
    for (int i = tid; i < 400; i += 352)
        sm.w1s[i / 20][i % 20] = W1g[(dir * 20 + i / 20) * 20 + (i % 20)];
    __syncthreads();

    if (tid < S) {
        float hrow[20];
        const float4* hp4 = (const float4*)sm.hist[tid];
#pragma unroll
        for (int i = 0; i < 5; i++) {
            float4 v = hp4[i];
            hrow[4 * i] = v.x; hrow[4 * i + 1] = v.y;
            hrow[4 * i + 2] = v.z; hrow[4 * i + 3] = v.w;
        }
        ull uacc[10];
#pragma unroll
        for (int v = 0; v < 10; v++) uacc[v] = 0ull;
#pragma unroll
        for (int j = 0; j < 20; j++) {
            ull hj = pk2(hrow[j], hrow[j]);
            const ull* wr = (const ull*)sm.w1s[j];
#pragma unroll
            for (int v = 0; v < 10; v++) ffma2(uacc[v], hj, wr[v]);
        }
        float* dst = (dir ? g_uB : g_uF) + ((size_t)tid * 32 + b) * 20;
#pragma unroll
        for (int v = 0; v < 10; v++) {
            float lo, hi;
            upk2(lo, hi, uacc[v]);
            *(float2*)&dst[2 * v] = make_float2(lo, hi);
        }
    }
}

// ---------------------------------------------------------------------------
// Emission: hid = tanh(uF[t+2]-uB[t+1]+b1 + uB[s0]-uF[s0+1]); out = hid@W2+b2
// Block per t; stage the 10 needed u-rows in smem; layer2 as tiled GEMM.
// ---------------------------------------------------------------------------
struct __align__(16) K3S {
    float uFs[10][20][32];   // [xi][v][b]
    float uBs[10][20][32];
    float hids[256 * 21];    // row stride 21 (bank-conflict-free)
    float W2s[20][56];
    float b2s[56];
    float b1s[20];
};

__global__ __launch_bounds__(256, 2) void k3_emis(
    const float* __restrict__ b1, const float* __restrict__ W2,
    const float* __restrict__ b2, float* __restrict__ out)
{
    extern __shared__ char raw[];
    K3S& sm = *(K3S*)raw;
    const int tid = threadIdx.x;
    const int t = blockIdx.x;
    const int xb = t - 7;

    for (int f = tid; f < 6400; f += 256) {
        int xi = f / 640, rem = f % 640, v = rem / 32, bb = rem % 32;
        int xx = xb + xi;
        xx = xx < 0 ? 0 : (xx > S - 1 ? S - 1 : xx);
        size_t gi = ((size_t)xx * 32 + bb) * 20 + v;
        sm.uFs[xi][v][bb] = g_uF[gi];
        sm.uBs[xi][v][bb] = g_uB[gi];
    }
    for (int i = tid; i < 20 * 56; i += 256) {
        int qq = i / 56, k = i % 56;
        sm.W2s[qq][k] = (k < 50) ? W2[qq * 50 + k] : 0.f;
    }
    if (tid < 56) sm.b2s[tid] = (tid < 50) ? b2[tid] : 0.f;
    if (tid < 20) sm.b1s[tid] = b1[tid];
    __syncthreads();

    // hid phase: thread = (l, b) row
    {
        const int l = tid >> 5, bb = tid & 31;
#pragma unroll
        for (int v = 0; v < 20; v++) {
            float hp = sm.uFs[9][v][bb] - sm.uBs[8][v][bb]
                     + sm.uBs[l][v][bb] - sm.uFs[l + 1][v][bb] + sm.b1s[v];
            sm.hids[tid * 21 + v] = tanh_ap(hp);
        }
    }
    __syncthreads();

    // layer2 GEMM: thread = (rowg of 4 rows, colg of 14 cols)
    {
        const int rowg = tid >> 2, cg = tid & 3;
        const int r0 = rowg * 4, kb = cg * 14;
        ull acc[4][7];
#pragma unroll
        for (int v = 0; v < 7; v++) {
            ull bv = pk2(sm.b2s[kb + 2 * v], sm.b2s[kb + 2 * v + 1]);
            acc[0][v] = bv; acc[1][v] = bv; acc[2][v] = bv; acc[3][v] = bv;
        }
#pragma unroll
        for (int qq = 0; qq < 20; qq++) {
            ull h0 = pk2(sm.hids[(r0 + 0) * 21 + qq], sm.hids[(r0 + 0) * 21 + qq]);
            ull h1 = pk2(sm.hids[(r0 + 1) * 21 + qq], sm.hids[(r0 + 1) * 21 + qq]);
            ull h2 = pk2(sm.hids[(r0 + 2) * 21 + qq], sm.hids[(r0 + 2) * 21 + qq]);
            ull h3 = pk2(sm.hids[(r0 + 3) * 21 + qq], sm.hids[(r0 + 3) * 21 + qq]);
            const ull* wr = (const ull*)&sm.W2s[qq][kb];
#pragma unroll
            for (int v = 0; v < 7; v++) {
                ull w = wr[v];
                ffma2(acc[0][v], h0, w);
                ffma2(acc[1][v], h1, w);
                ffma2(acc[2][v], h2, w);
                ffma2(acc[3][v], h3, w);
            }
        }
#pragma unroll
        for (int rr = 0; rr < 4; rr++) {
            int rw = r0 + rr;
            int l = rw >> 5, bb = rw & 31;
            bool valid = (t - 7 + l) >= 0;
            float* op = out + (((size_t)l * 256 + t) * 32 + bb) * 50 + kb;
#pragma unroll
            for (int v = 0; v < 7; v++) {
                int k = kb + 2 * v;
                if (k < 50) {
                    float lo, hi;
                    upk2(lo, hi, acc[rr][v]);
                    *(float2*)&op[2 * v] =
                        valid ? make_float2(lo, hi) : make_float2(NEGV, NEGV);
                }
            }
        }
    }
}

// ---------------------------------------------------------------------------
extern "C" void kernel_launch(void* const* d_in, const int* in_sizes, int n_in,
                              void* d_out, int out_size)
{
    const int*   x   = (const int*)d_in[0];
    const float* emb = (const float*)d_in[1];
    const float* Wif = (const float*)d_in[2];
    const float* Whf = (const float*)d_in[3];
    const float* bf  = (const float*)d_in[4];
    const float* Wib = (const float*)d_in[5];
    const float* Whb = (const float*)d_in[6];
    const float* bb  = (const float*)d_in[7];
    const float* W1  = (const float*)d_in[8];
    const float* b1  = (const float*)d_in[9];
    const float* W2  = (const float*)d_in[10];
    const float* b2  = (const float*)d_in[11];
    float* out = (float*)d_out;

    static bool attr_set = false;
    if (!attr_set) {
        cudaFuncSetAttribute(k12_fused, cudaFuncAttributeMaxDynamicSharedMemorySize,
                             (int)sizeof(SML));
        cudaFuncSetAttribute(k3_emis, cudaFuncAttributeMaxDynamicSharedMemorySize,
                             (int)sizeof(K3S));
        attr_set = true;
    }
    k12_fused<<<64, 352, sizeof(SML)>>>(x, emb, Wif, bf, Wib, bb, Whf, Whb, W1);
    k3_emis<<<256, 256, sizeof(K3S)>>>(b1, W2, b2, out);
}

// round 8
// speedup vs baseline: 1.0233x; 1.0233x over previous
#include <cuda_runtime.h>
#include <cstdint>
#include <cstddef>

#define NEGV -1e30f

constexpr int Bb = 32, Tt = 256, S = 258, Q = 20;

// u vectors, TRANSPOSED: u[s][v][b]  (coalesced for k3)
__device__ float g_uF[S * Q * Bb];
__device__ float g_uB[S * Q * Bb];

typedef unsigned long long ull;

// ---- helpers --------------------------------------------------------------
__device__ __forceinline__ ull pk2(float lo, float hi) {
    ull r;
    asm("mov.b64 %0, {%1, %2};" : "=l"(r) : "f"(lo), "f"(hi));
    return r;
}
__device__ __forceinline__ void upk2(float& lo, float& hi, ull v) {
    asm("mov.b64 {%0, %1}, %2;" : "=f"(lo), "=f"(hi) : "l"(v));
}
__device__ __forceinline__ void ffma2(ull& d, ull a, ull b) {
    asm("fma.rn.f32x2 %0, %1, %2, %0;" : "+l"(d) : "l"(a), "l"(b));
}
__device__ __forceinline__ void fadd2(ull& d, ull a) {
    asm("add.rn.f32x2 %0, %0, %1;" : "+l"(d) : "l"(a));
}
__device__ __forceinline__ float tanh_ap(float x) {
    float y;
    asm("tanh.approx.f32 %0, %1;" : "=f"(y) : "f"(x));
    return y;
}
__device__ __forceinline__ uint32_t s2u(const void* p) {
    uint32_t a;
    asm("{ .reg .u64 t; cvta.to.shared.u64 t, %1; cvt.u32.u64 %0, t; }"
        : "=r"(a) : "l"(p));
    return a;
}
__device__ __forceinline__ void cp_async16(uint32_t dst, const void* src) {
    asm volatile("cp.async.ca.shared.global [%0], [%1], 16;" :: "r"(dst), "l"(src));
}
__device__ __forceinline__ void cp_commit() {
    asm volatile("cp.async.commit_group;" ::: "memory");
}
template <int N> __device__ __forceinline__ void cp_wait() {
    asm volatile("cp.async.wait_group %0;" :: "n"(N) : "memory");
}
#define BAR96(id) asm volatile("bar.sync %0, %1;" :: "r"(id), "r"(96) : "memory")

// ---- fused kernel shared layout ------------------------------------------
struct __align__(16) SML {
    float pre[S][80];        // pre-gates [it][gt*20+q]              82560 B
    float W[128][80];        // W_ih                                 40960 B
    float A[2][32][128];     // embedding chunk ring                 32768 B
    float hist[S][20];       // h history (by position s)            20640 B
    float w1s[20][20];       // W1 rows for this dir                  1600 B
    float bias[80];
    float hsh[2][24];        // double-buffered h
    int   tok[260];
};

// ---------------------------------------------------------------------------
// Fused kernel: one block per (dir, batch), 352 threads.
//  warps 0..7: producers — chunked input-gate GEMM into sm.pre (cp.async ring)
//  warps 8..10 (96 thr): crew — lane ct = cell*4 + gate (all 4 gates of a
//    cell in ONE warp). Per step: 10-FFMA2 gate dot + 1 MUFU, 3x shfl to
//    gather the cell's acts, redundant c/h update, ONE bar.sync(96).
//  epilogue: u = hist @ W1dir -> g_uF/g_uB (transposed [s][v][b])
// ---------------------------------------------------------------------------
__global__ __launch_bounds__(352, 1) void k12_fused(
    const int* __restrict__ x, const float* __restrict__ emb,
    const float* __restrict__ Wif, const float* __restrict__ bfv,
    const float* __restrict__ Wib, const float* __restrict__ bbv,
    const float* __restrict__ Whf, const float* __restrict__ Whb,
    const float* __restrict__ W1g)
{
    extern __shared__ char raw[];
    SML& sm = *(SML*)raw;
    const int tid = threadIdx.x;
    const int dir = blockIdx.x >> 5;
    const int b = blockIdx.x & 31;
    const float* Wih = dir ? Wib : Wif;
    const float* bia = dir ? bbv : bfv;
    const float* Whh = dir ? Whb : Whf;
    const bool isProd = (tid < 256);
    const bool isCrew = (tid >= 256);

    if (tid < 256) sm.tok[tid + 1] = x[b * Tt + tid];
    if (tid == 256) { sm.tok[0] = 2; sm.tok[S - 1] = 3; }
    if (tid < 80) sm.bias[tid] = bia[tid];

    // ---- crew setup: ct = q*4 + gt ----
    const int ct = tid - 256;                // 0..95
    const int lane = tid & 31;
    const bool gact = (ct >= 0) && (ct < 80);
    const int ctc = gact ? ct : 76;          // clamp idle lanes to a real cell
    const int q = ctc >> 2, gt = ctc & 3;
    const int gcl = gt * 20 + q;             // source gate index
    const int cb = lane & ~3;                // cell base lane within warp
    const float szc = (gt == 2) ? 1.f : 0.5f;
    const float aac = (gt == 2) ? 1.f : 0.5f;
    const float bbc = (gt == 2) ? 0.f : 0.5f;
    const bool isG0 = gact && (gt == 0);
    ull wk[10];
    float creg = 0.f;
    if (isCrew) {
#pragma unroll
        for (int j = 0; j < 10; j++)
            wk[j] = pk2(Whh[(2 * j) * 80 + gcl], Whh[(2 * j + 1) * 80 + gcl]);
        if (ct < 48) { ((float*)sm.hsh)[ct] = 0.f; }
    }
    __syncthreads();

    // ---- producer prologue: W_ih, A chunk 0 ----
    if (isProd) {
#pragma unroll
        for (int i = 0; i < 10; i++) {
            int f = tid + i * 256;
            cp_async16(s2u((char*)sm.W + f * 16), Wih + f * 4);
        }
        cp_commit();
#pragma unroll
        for (int i = 0; i < 4; i++) {
            int f = tid + i * 256;
            int rr = f >> 5, k4 = f & 31;
            int s = dir ? (S - 1 - rr) : rr;
            cp_async16(s2u(&sm.A[0][rr][k4 * 4]),
                       emb + (size_t)sm.tok[s] * 128 + k4 * 4);
        }
        cp_commit();
    }

    const int r = tid >> 3;
    const int c0 = (tid & 7) * 10;

    // one crew step; prez preloaded; ONE barrier; par = it&1
    auto crew_step = [&](int it, float& prez, int next_it) {
        const int par = it & 1;
        const ulonglong2* hp = (const ulonglong2*)sm.hsh[par];
        ulonglong2 h0 = hp[0], h1 = hp[1], h2 = hp[2], h3 = hp[3], h4 = hp[4];
        ull a0 = pk2(prez, 0.f), a1 = 0ull;
        ffma2(a0, h0.x, wk[0]); ffma2(a1, h0.y, wk[1]);
        ffma2(a0, h1.x, wk[2]); ffma2(a1, h1.y, wk[3]);
        ffma2(a0, h2.x, wk[4]); ffma2(a1, h2.y, wk[5]);
        ffma2(a0, h3.x, wk[6]); ffma2(a1, h3.y, wk[7]);
        ffma2(a0, h4.x, wk[8]); ffma2(a1, h4.y, wk[9]);
        fadd2(a0, a1);
        float lo, hi;
        upk2(lo, hi, a0);
        float z = lo + hi;
        float av = fmaf(tanh_ap(szc * z), aac, bbc);   // my gate's activation
        float af = __shfl_sync(0xffffffffu, av, cb + 1);
        float ag = __shfl_sync(0xffffffffu, av, cb + 2);
        float ao = __shfl_sync(0xffffffffu, av, cb + 3);
        // redundant cell update (only meaningful/stored in gt==0 lanes)
        creg = fmaf(af, creg, av * ag);
        float h = ao * tanh_ap(creg);
        if (isG0) {
            sm.hsh[par ^ 1][q] = h;
            int s = dir ? (S - 1 - it) : it;
            sm.hist[s][q] = h;
        }
        if (next_it >= 0) prez = sm.pre[next_it][gcl];   // overlaps the bar
        BAR96(1);
    };

    for (int ch = 0; ch < 9; ch++) {
        if (isProd) {
            if (ch < 8) {
#pragma unroll
                for (int i = 0; i < 4; i++) {
                    int f = tid + i * 256;
                    int rr = f >> 5, k4 = f & 31;
                    int itn = (ch + 1) * 32 + rr;
                    if (itn < S) {
                        int s = dir ? (S - 1 - itn) : itn;
                        cp_async16(s2u(&sm.A[(ch + 1) & 1][rr][k4 * 4]),
                                   emb + (size_t)sm.tok[s] * 128 + k4 * 4);
                    }
                }
            }
            cp_commit();
            cp_wait<1>();

            int it = ch * 32 + r;
            if (it < S) {
                const float* Arow = sm.A[ch & 1][r];
                ull acc[5] = {0ull, 0ull, 0ull, 0ull, 0ull};
#pragma unroll 4
                for (int k = 0; k < 128; k++) {
                    float a = Arow[k];
                    ull ap = pk2(a, a);
#pragma unroll
                    for (int j = 0; j < 5; j++)
                        ffma2(acc[j], ap, *(const ull*)&sm.W[k][c0 + 2 * j]);
                }
#pragma unroll
                for (int j = 0; j < 5; j++) {
                    float lo, hi;
                    upk2(lo, hi, acc[j]);
                    float2 v;
                    v.x = lo + sm.bias[c0 + 2 * j];
                    v.y = hi + sm.bias[c0 + 2 * j + 1];
                    *(float2*)&sm.pre[it][c0 + 2 * j] = v;
                }
            }
        } else if (ch > 0) {
            int base = (ch - 1) * 32;
            float prez = sm.pre[base][gcl];
            for (int i = 0; i < 31; i++) crew_step(base + i, prez, base + i + 1);
            crew_step(base + 31, prez, -1);
        }
        __syncthreads();
    }

    if (isCrew) {
        float prez = sm.pre[256][gcl];
        crew_step(256, prez, 257);
        crew_step(257, prez, -1);
    }
    __syncthreads();

    // ---- u-phase: u[s] = hist[s] @ W1dir -> transposed [s][v][b]
    for (int i = tid; i < 400; i += 352)
        sm.w1s[i / 20][i % 20] = W1g[(dir * 20 + i / 20) * 20 + (i % 20)];
    __syncthreads();

    if (tid < S) {
        float hrow[20];
        const float4* hp4 = (const float4*)sm.hist[tid];
#pragma unroll
        for (int i = 0; i < 5; i++) {
            float4 v = hp4[i];
            hrow[4 * i] = v.x; hrow[4 * i + 1] = v.y;
            hrow[4 * i + 2] = v.z; hrow[4 * i + 3] = v.w;
        }
        ull uacc[10];
#pragma unroll
        for (int v = 0; v < 10; v++) uacc[v] = 0ull;
#pragma unroll
        for (int j = 0; j < 20; j++) {
            ull hj = pk2(hrow[j], hrow[j]);
            const ull* wr = (const ull*)sm.w1s[j];
#pragma unroll
            for (int v = 0; v < 10; v++) ffma2(uacc[v], hj, wr[v]);
        }
        float* ubase = (dir ? g_uB : g_uF) + (size_t)tid * (20 * 32) + b;
#pragma unroll
        for (int v = 0; v < 10; v++) {
            float lo, hi;
            upk2(lo, hi, uacc[v]);
            ubase[(2 * v) * 32] = lo;
            ubase[(2 * v + 1) * 32] = hi;
        }
    }
}

// ---------------------------------------------------------------------------
// Emission: hid = tanh(uF[t+2]-uB[t+1] + uB[s0]-uF[s0+1] + b1); out=hid@W2+b2
// Block per t, 512 threads: row = tid&255 -> (l,b), half = tid>>8 (28 cols).
// u loads fully coalesced (u is [s][v][b]); W2 broadcast from smem.
// ---------------------------------------------------------------------------
__global__ __launch_bounds__(512) void k3_emis(
    const float* __restrict__ b1, const float* __restrict__ W2,
    const float* __restrict__ b2, float* __restrict__ out)
{
    __shared__ __align__(16) float W2s[20][56];
    __shared__ float b2s[56];
    __shared__ float b1s[20];
    const int tid = threadIdx.x;
    const int t = blockIdx.x;

    for (int i = tid; i < 20 * 56; i += 512) {
        int qq = i / 56, k = i % 56;
        W2s[qq][k] = (k < 50) ? W2[qq * 50 + k] : 0.f;
    }
    if (tid < 56) b2s[tid] = (tid < 50) ? b2[tid] : 0.f;
    if (tid < 20) b1s[tid] = b1[tid];
    __syncthreads();

    const int row = tid & 255;
    const int half = tid >> 8;            // 0: cols 0..27, 1: cols 28..49
    const int l = row >> 5, b = row & 31;
    const int s0 = t - 7 + l;
    const int kb = half * 28;
    const int nv = half ? 11 : 14;        // float2 stores
    float* op = out + (((size_t)l * 256 + t) * 32 + b) * 50 + kb;

    if (s0 < 0) {
        for (int v = 0; v < nv; v++) *(float2*)&op[2 * v] = make_float2(NEGV, NEGV);
        return;
    }

    const float* uFe = g_uF + (size_t)(t + 2) * 640 + b;   // 640 = 20*32
    const float* uBe = g_uB + (size_t)(t + 1) * 640 + b;
    const float* uBs = g_uB + (size_t)s0 * 640 + b;
    const float* uFs = g_uF + (size_t)(s0 + 1) * 640 + b;

    float hid[20];
#pragma unroll
    for (int v = 0; v < 20; v++) {
        float hp = uFe[v * 32] - uBe[v * 32] + uBs[v * 32] - uFs[v * 32] + b1s[v];
        hid[v] = tanh_ap(hp);
    }

    ull acc[14];
#pragma unroll
    for (int v = 0; v < 14; v++) acc[v] = pk2(b2s[kb + 2 * v], b2s[kb + 2 * v + 1]);
#pragma unroll
    for (int qq = 0; qq < 20; qq++) {
        ull h2 = pk2(hid[qq], hid[qq]);
        const ull* wr = (const ull*)&W2s[qq][kb];
#pragma unroll
        for (int v = 0; v < 14; v++) ffma2(acc[v], h2, wr[v]);
    }
#pragma unroll
    for (int v = 0; v < 14; v++) {
        if (v < nv) {
            float lo, hi;
            upk2(lo, hi, acc[v]);
            *(float2*)&op[2 * v] = make_float2(lo, hi);
        }
    }
}

// ---------------------------------------------------------------------------
extern "C" void kernel_launch(void* const* d_in, const int* in_sizes, int n_in,
                              void* d_out, int out_size)
{
    const int*   x   = (const int*)d_in[0];
    const float* emb = (const float*)d_in[1];
    const float* Wif = (const float*)d_in[2];
    const float* Whf = (const float*)d_in[3];
    const float* bf  = (const float*)d_in[4];
    const float* Wib = (const float*)d_in[5];
    const float* Whb = (const float*)d_in[6];
    const float* bb  = (const float*)d_in[7];
    const float* W1  = (const float*)d_in[8];
    const float* b1  = (const float*)d_in[9];
    const float* W2  = (const float*)d_in[10];
    const float* b2  = (const float*)d_in[11];
    float* out = (float*)d_out;

    static bool attr_set = false;
    if (!attr_set) {
        cudaFuncSetAttribute(k12_fused, cudaFuncAttributeMaxDynamicSharedMemorySize,
                             (int)sizeof(SML));
        attr_set = true;
    }
    k12_fused<<<64, 352, sizeof(SML)>>>(x, emb, Wif, bf, Wib, bb, Whf, Whb, W1);
    k3_emis<<<256, 512>>>(b1, W2, b2, out);
}